// round 1
// baseline (speedup 1.0000x reference)
#include <cuda_runtime.h>
#include <math.h>

#define BB 32
#define TT 2048
#define DIN 64
#define HH 1024
#define DOUT 64
#define NSTEPS 60
#define C1 8
#define C2 16
#define C3 32
#define K1 4
#define K2 8
#define K3 16
#define LEN1 2045
#define LEN2 2038
#define LL 2023
#define KT1 1152          /* [ctx1(32) prev(64) h1(1024) pad(32)] */
#define KT23 2160         /* [ctx(32) h_prev(1024) h_self(1024) pad(80)] */
#define KC 18
#define CH1 64            /* KT1/KC */
#define CH23 120          /* KT23/KC */
#define G4 4096

typedef unsigned long long ull;

/* ------------- static device scratch (no runtime allocation) ------------- */
__device__ __align__(16) float d_Wcat1[G4 * KT1];
__device__ __align__(16) float d_Wcat2[G4 * KT23];
__device__ __align__(16) float d_Wcat3[G4 * KT23];
__device__ __align__(16) float d_cbias1[G4];
__device__ __align__(16) float d_cbias2[G4];
__device__ __align__(16) float d_cbias3[G4];
__device__ __align__(16) float d_woutT[HH * DOUT];
__device__ __align__(16) float d_buf1[BB * C1 * LEN1];
__device__ __align__(16) float d_buf2[BB * C2 * LEN2];
__device__ __align__(16) float d_enc[BB * LL * C3];
__device__ __align__(16) float d_gpart[KC * G4 * BB];
__device__ __align__(16) float d_xin1[BB * KT1];
__device__ __align__(16) float d_xin2[BB * KT23];
__device__ __align__(16) float d_xin3[BB * KT23];
__device__ __align__(16) float d_h1[BB * HH];
__device__ __align__(16) float d_c1[BB * HH];
__device__ __align__(16) float d_h2[BB * HH];
__device__ __align__(16) float d_c2[BB * HH];
__device__ __align__(16) float d_h3[BB * HH];
__device__ __align__(16) float d_c3[BB * HH];

/* ---------------------------- f32x2 helpers ------------------------------ */
__device__ __forceinline__ ull pack2(float x, float y) {
    ull r;
    asm("mov.b64 %0, {%1, %2};" : "=l"(r) : "f"(x), "f"(y));
    return r;
}
__device__ __forceinline__ void fma2(ull& acc, ull a, ull b) {
    asm("fma.rn.f32x2 %0, %1, %2, %0;" : "+l"(acc) : "l"(a), "l"(b));
}
__device__ __forceinline__ float sigf(float x) { return 1.f / (1.f + expf(-x)); }

/* ------------------------ weight concat precompute ----------------------- */
__global__ void wcat_kernel(int which, const float* __restrict__ wih,
                            const float* __restrict__ whh, int kx, int kt) {
    float* dst = which == 0 ? d_Wcat1 : which == 1 ? d_Wcat2 : d_Wcat3;
    size_t total = (size_t)G4 * kt;
    for (size_t idx = (size_t)blockIdx.x * blockDim.x + threadIdx.x; idx < total;
         idx += (size_t)gridDim.x * blockDim.x) {
        int n = (int)(idx / kt), col = (int)(idx % kt);
        float v;
        if (col < kx)
            v = wih[(size_t)n * kx + col];
        else if (col < kx + HH)
            v = whh[(size_t)n * HH + (col - kx)];
        else
            v = 0.f;
        dst[idx] = v;
    }
}

__global__ void misc_kernel(const float* __restrict__ bih1, const float* __restrict__ bhh1,
                            const float* __restrict__ bih2, const float* __restrict__ bhh2,
                            const float* __restrict__ bih3, const float* __restrict__ bhh3,
                            const float* __restrict__ wout) {
    int idx = blockIdx.x * 256 + threadIdx.x;
    if (idx < G4) {
        d_cbias1[idx] = bih1[idx] + bhh1[idx];
        d_cbias2[idx] = bih2[idx] + bhh2[idx];
        d_cbias3[idx] = bih3[idx] + bhh3[idx];
    }
    if (idx < HH * DOUT) {
        int hh = idx / DOUT, d = idx % DOUT;
        d_woutT[idx] = wout[(size_t)d * HH + hh];
    }
}

/* ------------------------------- init ------------------------------------ */
__global__ void init_kernel(const float* __restrict__ x) {
    const int NHC = 6 * BB * HH;              /* 196608 */
    const int NX1 = BB * KT1;                 /* 36864  */
    const int NX23 = BB * KT23;               /* 69120  */
    const int TOTAL = NHC + NX1 + 2 * NX23;
    for (int idx = blockIdx.x * blockDim.x + threadIdx.x; idx < TOTAL;
         idx += gridDim.x * blockDim.x) {
        int t = idx;
        if (t < NHC) {
            int which = t / (BB * HH);
            int off = t & (BB * HH - 1);
            float* p = which == 0 ? d_h1 : which == 1 ? d_c1 : which == 2 ? d_h2
                     : which == 3 ? d_c2 : which == 4 ? d_h3 : d_c3;
            p[off] = 0.f;
        } else if (t < NHC + NX1) {
            t -= NHC;
            int b = t / KT1, col = t % KT1;
            float v = 0.f;
            if (col >= 32 && col < 96)
                v = x[((size_t)b * TT + (TT - 1)) * DIN + (col - 32)];
            d_xin1[t] = v;
        } else {
            t -= NHC + NX1;
            if (t < NX23) d_xin2[t] = 0.f;
            else d_xin3[t - NX23] = 0.f;
        }
    }
}

/* ------------------------------ conv stack ------------------------------- */
__global__ void conv1_kernel(const float* __restrict__ x, const float* __restrict__ w,
                             const float* __restrict__ bias) {
    __shared__ float ws[DIN * K1];
    int c = blockIdx.y, b = blockIdx.z, tid = threadIdx.x;
    if (tid < DIN * K1) ws[tid] = w[c * DIN * K1 + tid];
    __syncthreads();
    int t = blockIdx.x * 256 + tid;
    if (t >= LEN1) return;
    const float* xp = x + ((size_t)b * TT + t) * DIN;
    float acc = bias[c];
#pragma unroll
    for (int k = 0; k < K1; k++)
#pragma unroll
        for (int i = 0; i < DIN; i++) acc += xp[k * DIN + i] * ws[i * K1 + k];
    d_buf1[((size_t)b * C1 + c) * LEN1 + t] = fmaxf(acc, 0.f);
}

__global__ void conv2_kernel(const float* __restrict__ w, const float* __restrict__ bias) {
    __shared__ float ws[C1 * K2];
    int c = blockIdx.y, b = blockIdx.z, tid = threadIdx.x;
    if (tid < C1 * K2) ws[tid] = w[c * C1 * K2 + tid];
    __syncthreads();
    int t = blockIdx.x * 256 + tid;
    if (t >= LEN2) return;
    float acc = bias[c];
    const float* ip = d_buf1 + (size_t)b * C1 * LEN1;
#pragma unroll
    for (int i = 0; i < C1; i++) {
        const float* row = ip + i * LEN1 + t;
#pragma unroll
        for (int k = 0; k < K2; k++) acc += row[k] * ws[i * K2 + k];
    }
    d_buf2[((size_t)b * C2 + c) * LEN2 + t] = fmaxf(acc, 0.f);
}

__global__ void conv3_kernel(const float* __restrict__ w, const float* __restrict__ bias) {
    __shared__ float ws[C3 * 257]; /* padded rows to kill bank conflicts */
    int b = blockIdx.y, tid = threadIdx.x;
    for (int i = tid; i < C3 * C2 * K3; i += 256) {
        int c = i / (C2 * K3), r = i % (C2 * K3);
        ws[c * 257 + r] = w[i];
    }
    __syncthreads();
    int c = tid & 31, tl = tid >> 5;
    int t = blockIdx.x * 8 + tl;
    if (t >= LL) return;
    float acc = bias[c];
    const float* ip = d_buf2 + (size_t)b * C2 * LEN2;
    const float* wp = ws + c * 257;
#pragma unroll
    for (int i = 0; i < C2; i++) {
        const float* row = ip + i * LEN2 + t;
#pragma unroll
        for (int k = 0; k < K3; k++) acc += row[k] * wp[i * K3 + k];
    }
    d_enc[((size_t)b * LL + t) * C3 + c] = fmaxf(acc, 0.f);
}

/* -------------- per-step prologue: 3x attention + y of prev step --------- */
__global__ __launch_bounds__(256) void pre_kernel(const float* __restrict__ wa1,
                                                  const float* __restrict__ wa2,
                                                  const float* __restrict__ wa3,
                                                  const float* __restrict__ bout,
                                                  int s, float* __restrict__ out) {
    __shared__ float red[256];
    __shared__ float hp[32];
    __shared__ float sc[LL];
    __shared__ float stot;
    int blk = blockIdx.x, tid = threadIdx.x;
    if (blk < 96) {
        int j = blk >> 5, b = blk & 31;
        const float* hb = (j == 0 ? d_h1 : j == 1 ? d_h2 : d_h3) + b * HH;
        const float* wa = j == 0 ? wa1 : j == 1 ? wa2 : wa3;
        int d = tid & 31, seg = tid >> 5;
        /* hp = h @ w_a  (32 values) */
        float part = 0.f;
        for (int hh = seg * 128; hh < seg * 128 + 128; hh++)
            part += hb[hh] * wa[hh * 32 + d];
        red[tid] = part;
        __syncthreads();
        if (tid < 32) {
            float sm = 0.f;
#pragma unroll
            for (int q = 0; q < 8; q++) sm += red[q * 32 + tid];
            hp[tid] = sm;
        }
        __syncthreads();
        const float* eb = d_enc + (size_t)b * LL * C3;
        /* pass 1: scores + max */
        float mx = -1e30f;
        for (int l = tid; l < LL; l += 256) {
            const float4* r = (const float4*)(eb + l * 32);
            float acc = 0.f;
#pragma unroll
            for (int q = 0; q < 8; q++) {
                float4 v = r[q];
                acc += v.x * hp[4 * q] + v.y * hp[4 * q + 1] + v.z * hp[4 * q + 2] +
                       v.w * hp[4 * q + 3];
            }
            sc[l] = acc;
            mx = fmaxf(mx, acc);
        }
        red[tid] = mx;
        __syncthreads();
        for (int st = 128; st > 0; st >>= 1) {
            if (tid < st) red[tid] = fmaxf(red[tid], red[tid + st]);
            __syncthreads();
        }
        mx = red[0];
        __syncthreads();
        /* pass 2: exp + sum */
        float ls = 0.f;
        for (int l = tid; l < LL; l += 256) {
            float e = expf(sc[l] - mx);
            sc[l] = e;
            ls += e;
        }
        red[tid] = ls;
        __syncthreads();
        for (int st = 128; st > 0; st >>= 1) {
            if (tid < st) red[tid] += red[tid + st];
            __syncthreads();
        }
        if (tid == 0) stot = red[0];
        __syncthreads();
        float inv = 1.f / stot;
        /* pass 3: ctx = sum e_l * enc_l */
        int g2 = tid >> 5;
        d = tid & 31;
        float ca = 0.f;
        for (int l = g2; l < LL; l += 8) ca += sc[l] * eb[l * 32 + d];
        __syncthreads();
        red[tid] = ca;
        __syncthreads();
        if (tid < 32) {
            float sm = 0.f;
#pragma unroll
            for (int q = 0; q < 8; q++) sm += red[q * 32 + tid];
            float* xin = j == 0 ? d_xin1 : j == 1 ? d_xin2 : d_xin3;
            int kt = j == 0 ? KT1 : KT23;
            xin[b * kt + tid] = sm * inv;
        }
    } else {
        /* y_{s-1} = h3 @ w_out.T + b_out -> d_out and xin1 prev-slot */
        if (s == 0) return;
        int b = blk - 96;
        int d = tid & 63, seg = tid >> 6;
        const float* hb = d_h3 + b * HH;
        float part = 0.f;
        for (int hh = seg * 256; hh < seg * 256 + 256; hh++)
            part += hb[hh] * d_woutT[hh * DOUT + d];
        red[tid] = part;
        __syncthreads();
        if (tid < 64) {
            float y = bout[tid];
#pragma unroll
            for (int q = 0; q < 4; q++) y += red[q * 64 + tid];
            out[((size_t)b * NSTEPS + (s - 1)) * DOUT + tid] = y;
            d_xin1[b * KT1 + 32 + tid] = y;
        }
    }
}

/* -------------------- LSTM gate GEMM (K-split, f32x2) -------------------- */
__global__ __launch_bounds__(256) void mm_kernel(int cell) {
    __shared__ __align__(16) float xs[CH23 * 34];
    const float* W = cell == 0 ? d_Wcat1 : cell == 1 ? d_Wcat2 : d_Wcat3;
    const float* X = cell == 0 ? d_xin1 : cell == 1 ? d_xin2 : d_xin3;
    const int KT = cell == 0 ? KT1 : KT23;
    const int KSUB = cell == 0 ? CH1 : CH23;

    int tid = threadIdx.x;
    int k0 = blockIdx.y * KSUB;
    int n0 = blockIdx.x * 512 + (tid >> 2) * 8;
    int b0 = (tid & 3) * 8;

    for (int idx = tid; idx < KSUB * BB; idx += 256) {
        int b = idx / KSUB, k = idx % KSUB;
        xs[k * 34 + b] = X[b * KT + k0 + k];
    }
    __syncthreads();

    ull acc[8][4];
#pragma unroll
    for (int i = 0; i < 8; i++)
#pragma unroll
        for (int p = 0; p < 4; p++) acc[i][p] = 0ULL;

    const float* Wp = W + (size_t)n0 * KT + k0;
    for (int kk = 0; kk < KSUB; kk += 4) {
        float4 w4[8];
#pragma unroll
        for (int i = 0; i < 8; i++) w4[i] = *(const float4*)(Wp + (size_t)i * KT + kk);
#pragma unroll
        for (int q = 0; q < 4; q++) {
            ull xp[4];
            const float* xr = xs + (kk + q) * 34 + b0;
#pragma unroll
            for (int p = 0; p < 4; p++) xp[p] = *(const ull*)(xr + 2 * p);
#pragma unroll
            for (int i = 0; i < 8; i++) {
                float wv = q == 0 ? w4[i].x : q == 1 ? w4[i].y : q == 2 ? w4[i].z : w4[i].w;
                ull wp2 = pack2(wv, wv);
#pragma unroll
                for (int p = 0; p < 4; p++) fma2(acc[i][p], wp2, xp[p]);
            }
        }
    }

    float* gpo = d_gpart + (size_t)blockIdx.y * G4 * BB;
#pragma unroll
    for (int i = 0; i < 8; i++) {
        float* row = gpo + (size_t)(n0 + i) * BB + b0;
#pragma unroll
        for (int p = 0; p < 4; p++) *(ull*)(row + 2 * p) = acc[i][p];
    }
}

/* ---------------- epilogue: reduce K-chunks + LSTM gates ----------------- */
__global__ __launch_bounds__(256) void epi_kernel(int cell) {
    const float* cb = cell == 0 ? d_cbias1 : cell == 1 ? d_cbias2 : d_cbias3;
    float* cst = cell == 0 ? d_c1 : cell == 1 ? d_c2 : d_c3;
    float* hst = cell == 0 ? d_h1 : cell == 1 ? d_h2 : d_h3;
    int idx = blockIdx.x * 256 + threadIdx.x;
    int j = idx >> 5, b = idx & 31;
    float g[4];
#pragma unroll
    for (int gt = 0; gt < 4; gt++) {
        float s = cb[gt * HH + j];
        const float* gp = d_gpart + (size_t)(gt * HH + j) * BB + b;
#pragma unroll
        for (int kc = 0; kc < KC; kc++) s += gp[(size_t)kc * G4 * BB];
        g[gt] = s;
    }
    float c = sigf(g[1]) * cst[b * HH + j] + sigf(g[0]) * tanhf(g[2]);
    float h = sigf(g[3]) * tanhf(c);
    cst[b * HH + j] = c;
    hst[b * HH + j] = h;
    if (cell == 0) {
        d_xin2[b * KT23 + 32 + j] = h;   /* input to cell2 this step */
        d_xin1[b * KT1 + 96 + j] = h;    /* recurrent h1 for next step */
    } else if (cell == 1) {
        d_xin3[b * KT23 + 32 + j] = h;   /* input to cell3 this step */
        d_xin2[b * KT23 + 1056 + j] = h; /* recurrent h2 for next step */
    } else {
        d_xin3[b * KT23 + 1056 + j] = h; /* recurrent h3 for next step */
    }
}

/* --------------------------- final y (step 59) --------------------------- */
__global__ void ylast_kernel(const float* __restrict__ bout, float* __restrict__ out) {
    __shared__ float red[256];
    int b = blockIdx.x, tid = threadIdx.x;
    int d = tid & 63, seg = tid >> 6;
    const float* hb = d_h3 + b * HH;
    float part = 0.f;
    for (int hh = seg * 256; hh < seg * 256 + 256; hh++)
        part += hb[hh] * d_woutT[hh * DOUT + d];
    red[tid] = part;
    __syncthreads();
    if (tid < 64) {
        float y = bout[tid];
#pragma unroll
        for (int q = 0; q < 4; q++) y += red[q * 64 + tid];
        out[((size_t)b * NSTEPS + (NSTEPS - 1)) * DOUT + tid] = y;
    }
}

/* ------------------------------ launcher --------------------------------- */
extern "C" void kernel_launch(void* const* d_in, const int* in_sizes, int n_in,
                              void* d_out, int out_size) {
    (void)in_sizes; (void)n_in; (void)out_size;
    const float* x    = (const float*)d_in[0];
    const float* w_c1 = (const float*)d_in[1];
    const float* b_c1 = (const float*)d_in[2];
    const float* w_c2 = (const float*)d_in[3];
    const float* b_c2 = (const float*)d_in[4];
    const float* w_c3 = (const float*)d_in[5];
    const float* b_c3 = (const float*)d_in[6];
    const float* w_a1 = (const float*)d_in[7];
    /* d_in[8] = b_a1: cancels in softmax */
    const float* w_a2 = (const float*)d_in[9];
    /* d_in[10] = b_a2 */
    const float* w_a3 = (const float*)d_in[11];
    /* d_in[12] = b_a3 */
    const float* wih1 = (const float*)d_in[13];
    const float* whh1 = (const float*)d_in[14];
    const float* bih1 = (const float*)d_in[15];
    const float* bhh1 = (const float*)d_in[16];
    const float* wih2 = (const float*)d_in[17];
    const float* whh2 = (const float*)d_in[18];
    const float* bih2 = (const float*)d_in[19];
    const float* bhh2 = (const float*)d_in[20];
    const float* wih3 = (const float*)d_in[21];
    const float* whh3 = (const float*)d_in[22];
    const float* bih3 = (const float*)d_in[23];
    const float* bhh3 = (const float*)d_in[24];
    const float* wout = (const float*)d_in[25];
    const float* bout = (const float*)d_in[26];
    float* out = (float*)d_out;

    wcat_kernel<<<2048, 256>>>(0, wih1, whh1, C3 + DIN, KT1);
    wcat_kernel<<<2048, 256>>>(1, wih2, whh2, C3 + HH, KT23);
    wcat_kernel<<<2048, 256>>>(2, wih3, whh3, C3 + HH, KT23);
    misc_kernel<<<256, 256>>>(bih1, bhh1, bih2, bhh2, bih3, bhh3, wout);
    init_kernel<<<1452, 256>>>(x);
    conv1_kernel<<<dim3(8, C1, BB), 256>>>(x, w_c1, b_c1);
    conv2_kernel<<<dim3(8, C2, BB), 256>>>(w_c2, b_c2);
    conv3_kernel<<<dim3(253, BB), 256>>>(w_c3, b_c3);

    for (int s = 0; s < NSTEPS; s++) {
        pre_kernel<<<128, 256>>>(w_a1, w_a2, w_a3, bout, s, out);
        mm_kernel<<<dim3(8, KC), 256>>>(0);
        epi_kernel<<<128, 256>>>(0);
        mm_kernel<<<dim3(8, KC), 256>>>(1);
        epi_kernel<<<128, 256>>>(1);
        mm_kernel<<<dim3(8, KC), 256>>>(2);
        epi_kernel<<<128, 256>>>(2);
    }
    ylast_kernel<<<32, 256>>>(bout, out);
}